// round 2
// baseline (speedup 1.0000x reference)
#include <cuda_runtime.h>
#include <math.h>

#define Bn   2
#define Cn   128
#define Hs   56
#define Nn   3136
#define NHn  4
#define HFn  341
#define TOK  (Bn*Nn)

__device__ __align__(256) float g_y   [TOK*Cn];
__device__ __align__(256) float g_tmp1[TOK*512];
__device__ __align__(256) float g_qs  [TOK*Cn];
__device__ __align__(256) float g_qn  [TOK*Cn];
__device__ __align__(256) float g_kl  [TOK*Cn];
__device__ __align__(256) float g_vl  [TOK*Cn];
__device__ __align__(256) float g_xp  [TOK*Cn];
__device__ __align__(256) float g_kvp [TOK*256];
__device__ __align__(256) float g_kp  [TOK*Cn];
__device__ __align__(256) float g_vp  [TOK*Cn];
__device__ __align__(256) float g_U   [TOK*Cn];
__device__ __align__(256) float g_Zp  [8*Nn];
__device__ __align__(256) float g_att [TOK*Cn];
__device__ __align__(256) float g_x2  [TOK*Cn];
__device__ __align__(256) float g_y2  [TOK*Cn];
__device__ __align__(256) float g_f1  [TOK*682];
__device__ __align__(256) float g_gb  [TOK*HFn];

__device__ __forceinline__ float gelu_exact(float x) {
    return 0.5f * x * (1.0f + erff(x * 0.70710678118654752f));
}

// ---------- LayerNorm: warp per token, channel-major input (stride Nn) ----------
__global__ void ln_kernel(const float* __restrict__ in, const float* __restrict__ w,
                          const float* __restrict__ bvec, float* __restrict__ out)
{
    int warp = blockIdx.x * 8 + (threadIdx.x >> 5);
    int lane = threadIdx.x & 31;
    int bb = warp / Nn, n = warp - bb * Nn;
    const float* p = in + (size_t)bb * (Cn*Nn) + n;
    float v[4], s = 0.f, s2 = 0.f;
#pragma unroll
    for (int k = 0; k < 4; k++) {
        int c = lane + 32*k;
        v[k] = p[(size_t)c * Nn];
        s += v[k]; s2 += v[k]*v[k];
    }
#pragma unroll
    for (int d = 1; d < 32; d <<= 1) {
        s  += __shfl_xor_sync(0xffffffffu, s,  d);
        s2 += __shfl_xor_sync(0xffffffffu, s2, d);
    }
    float mu = s * (1.0f/128.0f);
    float rstd = rsqrtf(s2*(1.0f/128.0f) - mu*mu + 1e-5f);
    float* o = out + (size_t)warp * 128;
#pragma unroll
    for (int k = 0; k < 4; k++) {
        int c = lane + 32*k;
        o[c] = (v[k]-mu)*rstd*w[c] + bvec[c];
    }
}

// ---------- GEMM: out[M,Nout] = A[M,Kd] @ W[Nout,Kd]^T + bias ----------
// BM=128 BN=64 BK=32, 256 thr, 8x4 micro. mode 0: plain; 1: +res same idx; 2: transposed channel-major +res
__global__ void __launch_bounds__(256) gemm_kernel(
    const float* __restrict__ A, int lda,
    const float* __restrict__ W, const float* __restrict__ bias,
    float* __restrict__ out, int ldo, int Nout, int Kd,
    int mode, const float* __restrict__ res)
{
    __shared__ __align__(16) float As[32][132];
    __shared__ __align__(16) float Wsm[32][68];
    const int m0 = blockIdx.y * 128;
    const int n0 = blockIdx.x * 64;
    const int tid = threadIdx.x;
    const int ty = tid >> 4, tx = tid & 15;
    const int lk = tid & 31, lrow = tid >> 5;

    float acc[8][4];
#pragma unroll
    for (int r = 0; r < 8; r++)
#pragma unroll
        for (int c = 0; c < 4; c++) acc[r][c] = 0.f;

    for (int k0 = 0; k0 < Kd; k0 += 32) {
        bool kok = (k0 + lk) < Kd;
#pragma unroll
        for (int i = 0; i < 16; i++) {
            int m = lrow + i*8;
            As[lk][m] = kok ? A[(size_t)(m0+m)*lda + k0 + lk] : 0.f;
        }
#pragma unroll
        for (int i = 0; i < 8; i++) {
            int nn = lrow + i*8;
            Wsm[lk][nn] = (kok && (n0+nn) < Nout) ? W[(size_t)(n0+nn)*Kd + k0 + lk] : 0.f;
        }
        __syncthreads();
#pragma unroll
        for (int kk = 0; kk < 32; kk++) {
            float4 a0 = *(const float4*)&As[kk][ty*8];
            float4 a1 = *(const float4*)&As[kk][ty*8+4];
            float4 w0 = *(const float4*)&Wsm[kk][tx*4];
            float av[8] = {a0.x,a0.y,a0.z,a0.w,a1.x,a1.y,a1.z,a1.w};
            float wv[4] = {w0.x,w0.y,w0.z,w0.w};
#pragma unroll
            for (int r = 0; r < 8; r++)
#pragma unroll
                for (int c = 0; c < 4; c++) acc[r][c] += av[r]*wv[c];
        }
        __syncthreads();
    }
#pragma unroll
    for (int r = 0; r < 8; r++) {
        int m = m0 + ty*8 + r;
#pragma unroll
        for (int c = 0; c < 4; c++) {
            int n = n0 + tx*4 + c;
            if (n >= Nout) continue;
            float v = acc[r][c] + bias[n];
            if (mode == 0) {
                out[(size_t)m*ldo + n] = v;
            } else if (mode == 1) {
                size_t idx = (size_t)m*ldo + n;
                out[idx] = v + res[idx];
            } else {
                int b = m / Nn, tn = m - b*Nn;
                size_t idx = ((size_t)b*Cn + n)*Nn + tn;
                out[idx] = v + res[idx];
            }
        }
    }
}

// ---------- pointwise after GEMM1: qs/qn/kl/vl head-major, xp token-major ----------
__global__ void pointwise1(const float* __restrict__ tmp1, const float* __restrict__ temp,
                           const float* __restrict__ qe, const float* __restrict__ plnw,
                           const float* __restrict__ plnb,
                           float* __restrict__ qs, float* __restrict__ qn,
                           float* __restrict__ kl, float* __restrict__ vl,
                           float* __restrict__ xp)
{
    int t = blockIdx.x * 8 + (threadIdx.x >> 5);
    int lane = threadIdx.x & 31;
    int bb = t / Nn, n = t - bb * Nn;
    int h = lane >> 3;
    int g = bb * NHn + h;
    const float4* row = (const float4*)(tmp1 + (size_t)t * 512);
    size_t ho = ((size_t)g * Nn + n) * 8 + (lane & 7);

    float4 q4 = row[lane];
    float ss = q4.x*q4.x + q4.y*q4.y + q4.z*q4.z + q4.w*q4.w;
    ss += __shfl_xor_sync(0xffffffffu, ss, 1);
    ss += __shfl_xor_sync(0xffffffffu, ss, 2);
    ss += __shfl_xor_sync(0xffffffffu, ss, 4);
    float inv = 1.0f / fmaxf(sqrtf(ss), 1e-12f);
    float4 qn4 = make_float4(q4.x*inv, q4.y*inv, q4.z*inv, q4.w*inv);
    float tv = temp[h];
    float sp = log1pf(__expf(tv));
    float4 qe4 = ((const float4*)qe)[h*8 + (lane & 7)];
    ((float4*)qn)[ho] = qn4;
    ((float4*)qs)[ho] = make_float4((qn4.x+qe4.x)*sp, (qn4.y+qe4.y)*sp,
                                    (qn4.z+qe4.z)*sp, (qn4.w+qe4.w)*sp);

    float4 k4 = row[32 + lane];
    float ks = k4.x*k4.x + k4.y*k4.y + k4.z*k4.z + k4.w*k4.w;
    ks += __shfl_xor_sync(0xffffffffu, ks, 1);
    ks += __shfl_xor_sync(0xffffffffu, ks, 2);
    ks += __shfl_xor_sync(0xffffffffu, ks, 4);
    float ki = 1.0f / fmaxf(sqrtf(ks), 1e-12f);
    ((float4*)kl)[ho] = make_float4(k4.x*ki, k4.y*ki, k4.z*ki, k4.w*ki);
    ((float4*)vl)[ho] = row[64 + lane];

    float4 s4 = row[96 + lane];
    float g0 = gelu_exact(s4.x), g1 = gelu_exact(s4.y);
    float g2 = gelu_exact(s4.z), g3 = gelu_exact(s4.w);
    float sm = g0+g1+g2+g3;
    float sq = g0*g0+g1*g1+g2*g2+g3*g3;
#pragma unroll
    for (int d = 1; d < 32; d <<= 1) {
        sm += __shfl_xor_sync(0xffffffffu, sm, d);
        sq += __shfl_xor_sync(0xffffffffu, sq, d);
    }
    float mu = sm*(1.0f/128.0f);
    float rstd = rsqrtf(sq*(1.0f/128.0f) - mu*mu + 1e-5f);
    int c = lane * 4;
    float4 o;
    o.x = (g0-mu)*rstd*plnw[c]   + plnb[c];
    o.y = (g1-mu)*rstd*plnw[c+1] + plnb[c+1];
    o.z = (g2-mu)*rstd*plnw[c+2] + plnb[c+2];
    o.w = (g3-mu)*rstd*plnw[c+3] + plnb[c+3];
    ((float4*)xp)[(size_t)t*32 + lane] = o;
}

// ---------- split kvp -> normalized kp / raw vp (head-major) ----------
__global__ void pointwise2(const float* __restrict__ kvp, float* __restrict__ kp,
                           float* __restrict__ vp)
{
    int t = blockIdx.x * 8 + (threadIdx.x >> 5);
    int lane = threadIdx.x & 31;
    int bb = t / Nn, n = t - bb * Nn;
    int h = lane >> 3;
    int g = bb * NHn + h;
    const float4* row = (const float4*)(kvp + (size_t)t * 256);
    size_t ho = ((size_t)g * Nn + n) * 8 + (lane & 7);

    float4 k4 = row[lane];
    float ks = k4.x*k4.x + k4.y*k4.y + k4.z*k4.z + k4.w*k4.w;
    ks += __shfl_xor_sync(0xffffffffu, ks, 1);
    ks += __shfl_xor_sync(0xffffffffu, ks, 2);
    ks += __shfl_xor_sync(0xffffffffu, ks, 4);
    float ki = 1.0f / fmaxf(sqrtf(ks), 1e-12f);
    ((float4*)kp)[ho] = make_float4(k4.x*ki, k4.y*ki, k4.z*ki, k4.w*ki);
    ((float4*)vp)[ho] = row[32 + lane];
}

// ---------- streaming pooled attention: U = exp(Qs Kp^T) Vp, Zp = rowsum ----------
__global__ void __launch_bounds__(256) attn_pool_kernel(
    const float* __restrict__ qs, const float* __restrict__ kp,
    const float* __restrict__ vp, float* __restrict__ U, float* __restrict__ Zp)
{
    __shared__ __align__(16) float Qt[32][68];
    __shared__ __align__(16) float Kt[32][68];
    __shared__ __align__(16) float Vs[64][36];
    __shared__ float Es[64][65];
    __shared__ float Zrow[64];
    const int g = blockIdx.y;
    const int q0 = blockIdx.x * 64;
    const int tid = threadIdx.x;
    const int ty = tid >> 4, tx = tid & 15;
    const int ur = tid >> 2, uc0 = (tid & 3) * 8;

    const float* qbase = qs + ((size_t)g*Nn + q0)*32;
    for (int i = tid; i < 2048; i += 256) Qt[i & 31][i >> 5] = qbase[i];
    if (tid < 64) Zrow[tid] = 0.f;
    float Uacc[8];
#pragma unroll
    for (int j = 0; j < 8; j++) Uacc[j] = 0.f;
    __syncthreads();

    for (int m0 = 0; m0 < Nn; m0 += 64) {
        const float* kbase = kp + ((size_t)g*Nn + m0)*32;
        const float* vbase = vp + ((size_t)g*Nn + m0)*32;
        for (int i = tid; i < 2048; i += 256) {
            Kt[i & 31][i >> 5] = kbase[i];
            Vs[i >> 5][i & 31] = vbase[i];
        }
        __syncthreads();
        float acc[4][4];
#pragma unroll
        for (int r = 0; r < 4; r++)
#pragma unroll
            for (int c = 0; c < 4; c++) acc[r][c] = 0.f;
#pragma unroll
        for (int kk = 0; kk < 32; kk++) {
            float4 a = *(const float4*)&Qt[kk][ty*4];
            float4 b = *(const float4*)&Kt[kk][tx*4];
            float av[4] = {a.x,a.y,a.z,a.w};
            float bv[4] = {b.x,b.y,b.z,b.w};
#pragma unroll
            for (int r = 0; r < 4; r++)
#pragma unroll
                for (int c = 0; c < 4; c++) acc[r][c] += av[r]*bv[c];
        }
#pragma unroll
        for (int r = 0; r < 4; r++)
#pragma unroll
            for (int c = 0; c < 4; c++)
                Es[ty*4+r][tx*4+c] = __expf(acc[r][c]);
        __syncthreads();
        float z = 0.f;
#pragma unroll 8
        for (int k = 0; k < 64; k++) {
            float e = Es[ur][k];
            z += e;
            float4 v0 = *(const float4*)&Vs[k][uc0];
            float4 v1 = *(const float4*)&Vs[k][uc0+4];
            Uacc[0] += e*v0.x; Uacc[1] += e*v0.y; Uacc[2] += e*v0.z; Uacc[3] += e*v0.w;
            Uacc[4] += e*v1.x; Uacc[5] += e*v1.y; Uacc[6] += e*v1.z; Uacc[7] += e*v1.w;
        }
        if ((tid & 3) == 0) Zrow[ur] += z;
        __syncthreads();
    }
    float* ub = U + ((size_t)g*Nn + q0 + ur)*32 + uc0;
#pragma unroll
    for (int j = 0; j < 8; j++) ub[j] = Uacc[j];
    if (tid < 64) Zp[(size_t)g*Nn + q0 + tid] = Zrow[tid];
}

// ---------- finalize: local 3x3 logits + learnable tokens + softmax combine ----------
__global__ void attn_finalize(
    const float* __restrict__ qs, const float* __restrict__ qn,
    const float* __restrict__ kl, const float* __restrict__ vl,
    const float* __restrict__ U, const float* __restrict__ Zp,
    const float* __restrict__ lt, const float* __restrict__ lb,
    float* __restrict__ xo)
{
    int warp = blockIdx.x * 8 + (threadIdx.x >> 5);
    int lane = threadIdx.x & 31;
    int g = warp / Nn, n = warp - g*Nn;
    int b = g >> 2, h = g & 3;
    int hh = n / Hs, ww = n - hh*Hs;
    size_t qi = ((size_t)g*Nn + n)*32 + lane;
    float q = qs[qi];
    float qv = qn[qi];
    float z = 0.f, res = 0.f, res2 = 0.f;
#pragma unroll
    for (int k = 0; k < 9; k++) {
        int h2 = hh + k/3 - 1, w2 = ww + (k%3) - 1;
        bool ok = (h2 >= 0 && h2 < Hs && w2 >= 0 && w2 < Hs);
        int nb = h2*Hs + w2;
        float kv = 0.f, vv = 0.f;
        if (ok) {
            size_t bi = ((size_t)g*Nn + nb)*32 + lane;
            kv = kl[bi]; vv = vl[bi];
        }
        float lg = q * kv;
        float wl = qv * lt[(h*32 + lane)*9 + k];
#pragma unroll
        for (int d = 16; d >= 1; d >>= 1) {
            lg += __shfl_xor_sync(0xffffffffu, lg, d);
            wl += __shfl_xor_sync(0xffffffffu, wl, d);
        }
        float e = __expf(lg);
        z += e;
        res  += e * vv;
        res2 += (wl + lb[h*9 + k]) * vv;
    }
    float Z = Zp[(size_t)g*Nn + n] + z;
    float o = (U[qi] + res) / Z + res2;
    xo[((size_t)(b*Nn + n))*128 + h*32 + lane] = o;
}

// ---------- depthwise 3x3 + gelu * v ----------
__global__ void dwconv_kernel(const float* __restrict__ f1, const float* __restrict__ dww,
                              const float* __restrict__ dwb, float* __restrict__ gout)
{
    int t = blockIdx.x;
    int c = threadIdx.x;
    if (c >= HFn) return;
    int b = t / Nn, n = t - b*Nn;
    int hh = n / Hs, ww = n - hh*Hs;
    float acc = dwb[c];
#pragma unroll
    for (int k = 0; k < 9; k++) {
        int h2 = hh + k/3 - 1, w2 = ww + (k%3) - 1;
        if (h2 < 0 || h2 >= Hs || w2 < 0 || w2 >= Hs) continue;
        acc += f1[((size_t)(b*Nn + h2*Hs + w2))*682 + c] * dww[c*9 + k];
    }
    float v = f1[(size_t)t*682 + 341 + c];
    gout[(size_t)t*HFn + c] = gelu_exact(acc) * v;
}

extern "C" void kernel_launch(void* const* d_in, const int* in_sizes, int n_in,
                              void* d_out, int out_size)
{
    const float* x      = (const float*)d_in[0];
    const float* n1w    = (const float*)d_in[1];
    const float* n1b    = (const float*)d_in[2];
    const float* q_w    = (const float*)d_in[3];
    const float* q_b    = (const float*)d_in[4];
    const float* kv_w   = (const float*)d_in[5];
    const float* kv_b   = (const float*)d_in[6];
    const float* temp   = (const float*)d_in[7];
    const float* qe     = (const float*)d_in[8];
    const float* lt     = (const float*)d_in[9];
    const float* lb     = (const float*)d_in[10];
    const float* sr_w   = (const float*)d_in[11];
    const float* sr_b   = (const float*)d_in[12];
    const float* plnw   = (const float*)d_in[13];
    const float* plnb   = (const float*)d_in[14];
    const float* proj_w = (const float*)d_in[15];
    const float* proj_b = (const float*)d_in[16];
    const float* n2w    = (const float*)d_in[17];
    const float* n2b    = (const float*)d_in[18];
    const float* fc1_w  = (const float*)d_in[19];
    const float* fc1_b  = (const float*)d_in[20];
    const float* dw_w   = (const float*)d_in[21];
    const float* dw_b   = (const float*)d_in[22];
    const float* fc2_w  = (const float*)d_in[23];
    const float* fc2_b  = (const float*)d_in[24];
    float* out = (float*)d_out;

    float *yb, *t1, *qsb, *qnb, *klb, *vlb, *xpb, *kvpb, *kpb, *vpb;
    float *Ub, *Zpb, *attb, *x2b, *y2b, *f1b, *gbb;
    cudaGetSymbolAddress((void**)&yb,   g_y);
    cudaGetSymbolAddress((void**)&t1,   g_tmp1);
    cudaGetSymbolAddress((void**)&qsb,  g_qs);
    cudaGetSymbolAddress((void**)&qnb,  g_qn);
    cudaGetSymbolAddress((void**)&klb,  g_kl);
    cudaGetSymbolAddress((void**)&vlb,  g_vl);
    cudaGetSymbolAddress((void**)&xpb,  g_xp);
    cudaGetSymbolAddress((void**)&kvpb, g_kvp);
    cudaGetSymbolAddress((void**)&kpb,  g_kp);
    cudaGetSymbolAddress((void**)&vpb,  g_vp);
    cudaGetSymbolAddress((void**)&Ub,   g_U);
    cudaGetSymbolAddress((void**)&Zpb,  g_Zp);
    cudaGetSymbolAddress((void**)&attb, g_att);
    cudaGetSymbolAddress((void**)&x2b,  g_x2);
    cudaGetSymbolAddress((void**)&y2b,  g_y2);
    cudaGetSymbolAddress((void**)&f1b,  g_f1);
    cudaGetSymbolAddress((void**)&gbb,  g_gb);

    ln_kernel<<<TOK/8, 256>>>(x, n1w, n1b, yb);
    gemm_kernel<<<dim3(2,49), 256>>>(yb, 128, q_w,  q_b,  t1,       512, 128, 128, 0, nullptr);
    gemm_kernel<<<dim3(4,49), 256>>>(yb, 128, kv_w, kv_b, t1 + 128, 512, 256, 128, 0, nullptr);
    gemm_kernel<<<dim3(2,49), 256>>>(yb, 128, sr_w, sr_b, t1 + 384, 512, 128, 128, 0, nullptr);
    pointwise1<<<TOK/8, 256>>>(t1, temp, qe, plnw, plnb, qsb, qnb, klb, vlb, xpb);
    gemm_kernel<<<dim3(4,49), 256>>>(xpb, 128, kv_w, kv_b, kvpb, 256, 256, 128, 0, nullptr);
    pointwise2<<<TOK/8, 256>>>(kvpb, kpb, vpb);
    attn_pool_kernel<<<dim3(49,8), 256>>>(qsb, kpb, vpb, Ub, Zpb);
    attn_finalize<<<Nn, 256>>>(qsb, qnb, klb, vlb, Ub, Zpb, lt, lb, attb);
    gemm_kernel<<<dim3(2,49), 256>>>(attb, 128, proj_w, proj_b, x2b, 128, 128, 128, 1, x);
    ln_kernel<<<TOK/8, 256>>>(x2b, n2w, n2b, y2b);
    gemm_kernel<<<dim3(11,49), 256>>>(y2b, 128, fc1_w, fc1_b, f1b, 682, 682, 128, 0, nullptr);
    dwconv_kernel<<<TOK, 384>>>(f1b, dw_w, dw_b, gbb);
    gemm_kernel<<<dim3(2,49), 256>>>(gbb, 341, fc2_w, fc2_b, out, 128, 128, 341, 2, x2b);
}

// round 5
// speedup vs baseline: 1.8895x; 1.8895x over previous
#include <cuda_runtime.h>
#include <cuda_fp16.h>
#include <math.h>

#define Bn   2
#define Cn   128
#define Hs   56
#define Nn   3136
#define NHn  4
#define HFn  341
#define TOK  (Bn*Nn)

__device__ __align__(256) float g_y   [TOK*Cn];
__device__ __align__(256) float g_tmp1[TOK*512];
__device__ __align__(256) float g_qs  [TOK*Cn];
__device__ __align__(256) float g_qn  [TOK*Cn];
__device__ __align__(256) float g_kl  [TOK*Cn];
__device__ __align__(256) float g_vl  [TOK*Cn];
__device__ __align__(256) float g_xp  [TOK*Cn];
__device__ __align__(256) float g_kvp [TOK*256];
__device__ __align__(256) float g_kp  [TOK*Cn];
__device__ __align__(256) float g_vp  [TOK*Cn];
__device__ __align__(256) float g_U   [TOK*Cn];
__device__ __align__(256) float g_Zp  [8*Nn];
__device__ __align__(256) float g_att [TOK*Cn];
__device__ __align__(256) float g_x2  [TOK*Cn];
__device__ __align__(256) float g_y2  [TOK*Cn];
__device__ __align__(256) float g_f1  [TOK*682];
__device__ __align__(256) float g_gb  [TOK*HFn];

__device__ __forceinline__ float gelu_exact(float x) {
    return 0.5f * x * (1.0f + erff(x * 0.70710678118654752f));
}

__device__ __forceinline__ unsigned h2pack(float a, float b) {
    __half2 h = __floats2half2_rn(a, b);
    return *(unsigned*)&h;
}

__device__ __forceinline__ void mma16816(float* c, const unsigned* a, unsigned b0, unsigned b1) {
    asm volatile("mma.sync.aligned.m16n8k16.row.col.f32.f16.f16.f32 "
        "{%0,%1,%2,%3}, {%4,%5,%6,%7}, {%8,%9}, {%0,%1,%2,%3};"
        : "+f"(c[0]), "+f"(c[1]), "+f"(c[2]), "+f"(c[3])
        : "r"(a[0]), "r"(a[1]), "r"(a[2]), "r"(a[3]), "r"(b0), "r"(b1));
}

// ---------- LayerNorm: warp per token, channel-major input (stride Nn) ----------
__global__ void ln_kernel(const float* __restrict__ in, const float* __restrict__ w,
                          const float* __restrict__ bvec, float* __restrict__ out)
{
    int warp = blockIdx.x * 8 + (threadIdx.x >> 5);
    int lane = threadIdx.x & 31;
    int bb = warp / Nn, n = warp - bb * Nn;
    const float* p = in + (size_t)bb * (Cn*Nn) + n;
    float v[4], s = 0.f, s2 = 0.f;
#pragma unroll
    for (int k = 0; k < 4; k++) {
        int c = lane + 32*k;
        v[k] = p[(size_t)c * Nn];
        s += v[k]; s2 += v[k]*v[k];
    }
#pragma unroll
    for (int d = 1; d < 32; d <<= 1) {
        s  += __shfl_xor_sync(0xffffffffu, s,  d);
        s2 += __shfl_xor_sync(0xffffffffu, s2, d);
    }
    float mu = s * (1.0f/128.0f);
    float rstd = rsqrtf(s2*(1.0f/128.0f) - mu*mu + 1e-5f);
    float* o = out + (size_t)warp * 128;
#pragma unroll
    for (int k = 0; k < 4; k++) {
        int c = lane + 32*k;
        o[c] = (v[k]-mu)*rstd*w[c] + bvec[c];
    }
}

// ---------- GEMM: out[M,Nout] = A[M,Kd] @ W[Nout,Kd]^T + bias ----------
__global__ void __launch_bounds__(256) gemm_kernel(
    const float* __restrict__ A, int lda,
    const float* __restrict__ W, const float* __restrict__ bias,
    float* __restrict__ out, int ldo, int Nout, int Kd,
    int mode, const float* __restrict__ res)
{
    __shared__ __align__(16) float As[32][132];
    __shared__ __align__(16) float Wsm[32][68];
    const int m0 = blockIdx.y * 128;
    const int n0 = blockIdx.x * 64;
    const int tid = threadIdx.x;
    const int ty = tid >> 4, tx = tid & 15;
    const int lk = tid & 31, lrow = tid >> 5;

    float acc[8][4];
#pragma unroll
    for (int r = 0; r < 8; r++)
#pragma unroll
        for (int c = 0; c < 4; c++) acc[r][c] = 0.f;

    for (int k0 = 0; k0 < Kd; k0 += 32) {
        bool kok = (k0 + lk) < Kd;
#pragma unroll
        for (int i = 0; i < 16; i++) {
            int m = lrow + i*8;
            As[lk][m] = kok ? A[(size_t)(m0+m)*lda + k0 + lk] : 0.f;
        }
#pragma unroll
        for (int i = 0; i < 8; i++) {
            int nn = lrow + i*8;
            Wsm[lk][nn] = (kok && (n0+nn) < Nout) ? W[(size_t)(n0+nn)*Kd + k0 + lk] : 0.f;
        }
        __syncthreads();
#pragma unroll
        for (int kk = 0; kk < 32; kk++) {
            float4 a0 = *(const float4*)&As[kk][ty*8];
            float4 a1 = *(const float4*)&As[kk][ty*8+4];
            float4 w0 = *(const float4*)&Wsm[kk][tx*4];
            float av[8] = {a0.x,a0.y,a0.z,a0.w,a1.x,a1.y,a1.z,a1.w};
            float wv[4] = {w0.x,w0.y,w0.z,w0.w};
#pragma unroll
            for (int r = 0; r < 8; r++)
#pragma unroll
                for (int c = 0; c < 4; c++) acc[r][c] += av[r]*wv[c];
        }
        __syncthreads();
    }
#pragma unroll
    for (int r = 0; r < 8; r++) {
        int m = m0 + ty*8 + r;
#pragma unroll
        for (int c = 0; c < 4; c++) {
            int n = n0 + tx*4 + c;
            if (n >= Nout) continue;
            float v = acc[r][c] + bias[n];
            if (mode == 0) {
                out[(size_t)m*ldo + n] = v;
            } else if (mode == 1) {
                size_t idx = (size_t)m*ldo + n;
                out[idx] = v + res[idx];
            } else {
                int b = m / Nn, tn = m - b*Nn;
                size_t idx = ((size_t)b*Cn + n)*Nn + tn;
                out[idx] = v + res[idx];
            }
        }
    }
}

// ---------- pointwise after GEMM1 ----------
__global__ void pointwise1(const float* __restrict__ tmp1, const float* __restrict__ temp,
                           const float* __restrict__ qe, const float* __restrict__ plnw,
                           const float* __restrict__ plnb,
                           float* __restrict__ qs, float* __restrict__ qn,
                           float* __restrict__ kl, float* __restrict__ vl,
                           float* __restrict__ xp)
{
    int t = blockIdx.x * 8 + (threadIdx.x >> 5);
    int lane = threadIdx.x & 31;
    int bb = t / Nn, n = t - bb * Nn;
    int h = lane >> 3;
    int g = bb * NHn + h;
    const float4* row = (const float4*)(tmp1 + (size_t)t * 512);
    size_t ho = ((size_t)g * Nn + n) * 8 + (lane & 7);

    float4 q4 = row[lane];
    float ss = q4.x*q4.x + q4.y*q4.y + q4.z*q4.z + q4.w*q4.w;
    ss += __shfl_xor_sync(0xffffffffu, ss, 1);
    ss += __shfl_xor_sync(0xffffffffu, ss, 2);
    ss += __shfl_xor_sync(0xffffffffu, ss, 4);
    float inv = 1.0f / fmaxf(sqrtf(ss), 1e-12f);
    float4 qn4 = make_float4(q4.x*inv, q4.y*inv, q4.z*inv, q4.w*inv);
    float tv = temp[h];
    float sp = log1pf(__expf(tv));
    float4 qe4 = ((const float4*)qe)[h*8 + (lane & 7)];
    ((float4*)qn)[ho] = qn4;
    ((float4*)qs)[ho] = make_float4((qn4.x+qe4.x)*sp, (qn4.y+qe4.y)*sp,
                                    (qn4.z+qe4.z)*sp, (qn4.w+qe4.w)*sp);

    float4 k4 = row[32 + lane];
    float ks = k4.x*k4.x + k4.y*k4.y + k4.z*k4.z + k4.w*k4.w;
    ks += __shfl_xor_sync(0xffffffffu, ks, 1);
    ks += __shfl_xor_sync(0xffffffffu, ks, 2);
    ks += __shfl_xor_sync(0xffffffffu, ks, 4);
    float ki = 1.0f / fmaxf(sqrtf(ks), 1e-12f);
    ((float4*)kl)[ho] = make_float4(k4.x*ki, k4.y*ki, k4.z*ki, k4.w*ki);
    ((float4*)vl)[ho] = row[64 + lane];

    float4 s4 = row[96 + lane];
    float g0 = gelu_exact(s4.x), g1 = gelu_exact(s4.y);
    float g2 = gelu_exact(s4.z), g3 = gelu_exact(s4.w);
    float sm = g0+g1+g2+g3;
    float sq = g0*g0+g1*g1+g2*g2+g3*g3;
#pragma unroll
    for (int d = 1; d < 32; d <<= 1) {
        sm += __shfl_xor_sync(0xffffffffu, sm, d);
        sq += __shfl_xor_sync(0xffffffffu, sq, d);
    }
    float mu = sm*(1.0f/128.0f);
    float rstd = rsqrtf(sq*(1.0f/128.0f) - mu*mu + 1e-5f);
    int c = lane * 4;
    float4 o;
    o.x = (g0-mu)*rstd*plnw[c]   + plnb[c];
    o.y = (g1-mu)*rstd*plnw[c+1] + plnb[c+1];
    o.z = (g2-mu)*rstd*plnw[c+2] + plnb[c+2];
    o.w = (g3-mu)*rstd*plnw[c+3] + plnb[c+3];
    ((float4*)xp)[(size_t)t*32 + lane] = o;
}

// ---------- split kvp -> normalized kp / raw vp (head-major) ----------
__global__ void pointwise2(const float* __restrict__ kvp, float* __restrict__ kp,
                           float* __restrict__ vp)
{
    int t = blockIdx.x * 8 + (threadIdx.x >> 5);
    int lane = threadIdx.x & 31;
    int bb = t / Nn, n = t - bb * Nn;
    int h = lane >> 3;
    int g = bb * NHn + h;
    const float4* row = (const float4*)(kvp + (size_t)t * 256);
    size_t ho = ((size_t)g * Nn + n) * 8 + (lane & 7);

    float4 k4 = row[lane];
    float ks = k4.x*k4.x + k4.y*k4.y + k4.z*k4.z + k4.w*k4.w;
    ks += __shfl_xor_sync(0xffffffffu, ks, 1);
    ks += __shfl_xor_sync(0xffffffffu, ks, 2);
    ks += __shfl_xor_sync(0xffffffffu, ks, 4);
    float ki = 1.0f / fmaxf(sqrtf(ks), 1e-12f);
    ((float4*)kp)[ho] = make_float4(k4.x*ki, k4.y*ki, k4.z*ki, k4.w*ki);
    ((float4*)vp)[ho] = row[32 + lane];
}

// ---------- HMMA streaming pooled attention ----------
// grid (49, 8), 128 threads (4 warps). Warp = 16 q rows, CTA = 64 q rows.
// KV chunks of 128. fp16 hi/lo split QK^T, fp32 exp+Z, fp16 E@V with fp32 acc.
__global__ void __launch_bounds__(128) attn_pool_mma(
    const float* __restrict__ qs, const float* __restrict__ kp,
    const float* __restrict__ vp, float* __restrict__ U, float* __restrict__ Zp)
{
    __shared__ __half Khi[128][36];
    __shared__ __half Klo[128][36];
    __shared__ __half Vt[32][132];

    const int g  = blockIdx.y;
    const int q0 = blockIdx.x * 64;
    const int tid = threadIdx.x;
    const int warp = tid >> 5;
    const int lane = tid & 31;
    const int r  = lane >> 2;        // row within 16-row tile
    const int c2 = (lane & 3) * 2;   // col pair

    // ---- Q fragments (hi/lo), 2 k-steps of 16 ----
    unsigned qhi[2][4], qlo[2][4];
    {
        const float* q0p = qs + ((size_t)g*Nn + q0 + warp*16 + r)*32;
        const float* q8p = q0p + 8*32;
#pragma unroll
        for (int ks = 0; ks < 2; ks++) {
            int d0 = ks*16 + c2;
            float x[4][2];
            x[0][0] = q0p[d0];   x[0][1] = q0p[d0+1];
            x[1][0] = q8p[d0];   x[1][1] = q8p[d0+1];
            x[2][0] = q0p[d0+8]; x[2][1] = q0p[d0+9];
            x[3][0] = q8p[d0+8]; x[3][1] = q8p[d0+9];
#pragma unroll
            for (int i = 0; i < 4; i++) {
                float a = x[i][0], b = x[i][1];
                float ah = __half2float(__float2half_rn(a));
                float bh = __half2float(__float2half_rn(b));
                qhi[ks][i] = h2pack(ah, bh);
                qlo[ks][i] = h2pack(a - ah, b - bh);
            }
        }
    }

    float uf[4][4];
#pragma unroll
    for (int t = 0; t < 4; t++)
#pragma unroll
        for (int i = 0; i < 4; i++) uf[t][i] = 0.f;
    float z0 = 0.f, z1 = 0.f;

    const int NCH = 25;
    for (int ch = 0; ch < NCH; ch++) {
        const int m0 = ch * 128;
        // ---- load & convert K,V chunk: thread -> one kv row ----
        {
            int kvr = m0 + tid;
            bool ok = kvr < Nn;
            const float4* kr = (const float4*)(kp + ((size_t)g*Nn + (ok ? kvr : 0))*32);
            const float4* vr = (const float4*)(vp + ((size_t)g*Nn + (ok ? kvr : 0))*32);
#pragma unroll
            for (int j = 0; j < 8; j++) {
                float4 f = ok ? kr[j] : make_float4(0.f,0.f,0.f,0.f);
                float e[4] = {f.x, f.y, f.z, f.w};
#pragma unroll
                for (int u = 0; u < 4; u++) {
                    float hv = __half2float(__float2half_rn(e[u]));
                    Khi[tid][j*4+u] = __float2half_rn(e[u]);
                    Klo[tid][j*4+u] = __float2half_rn(e[u] - hv);
                }
                float4 v = ok ? vr[j] : make_float4(0.f,0.f,0.f,0.f);
                Vt[j*4+0][tid] = __float2half_rn(v.x);
                Vt[j*4+1][tid] = __float2half_rn(v.y);
                Vt[j*4+2][tid] = __float2half_rn(v.z);
                Vt[j*4+3][tid] = __float2half_rn(v.w);
            }
        }
        __syncthreads();

        // ---- S = Q K^T over 16 n8-tiles ----
        float sf[16][4];
#pragma unroll
        for (int t = 0; t < 16; t++)
#pragma unroll
            for (int i = 0; i < 4; i++) sf[t][i] = 0.f;

#pragma unroll
        for (int ks = 0; ks < 2; ks++) {
            int d0 = ks*16 + c2;
#pragma unroll
            for (int t = 0; t < 16; t++) {
                int kv = t*8 + (lane >> 2);
                unsigned bh0 = *(const unsigned*)&Khi[kv][d0];
                unsigned bh1 = *(const unsigned*)&Khi[kv][d0+8];
                unsigned bl0 = *(const unsigned*)&Klo[kv][d0];
                unsigned bl1 = *(const unsigned*)&Klo[kv][d0+8];
                mma16816(sf[t], qhi[ks], bh0, bh1);
                mma16816(sf[t], qhi[ks], bl0, bl1);
                mma16816(sf[t], qlo[ks], bh0, bh1);
            }
        }

        // ---- exp + Z + pack to A frags ----
        const int tlim = (m0 + 128 <= Nn) ? 16 : 8;   // 3136 boundary hits tile 8 exactly
        unsigned ep[32];
#pragma unroll
        for (int t = 0; t < 16; t++) {
            if (t < tlim) {
                float e0 = __expf(sf[t][0]);
                float e1 = __expf(sf[t][1]);
                float e2 = __expf(sf[t][2]);
                float e3 = __expf(sf[t][3]);
                z0 += e0 + e1;
                z1 += e2 + e3;
                ep[2*t]   = h2pack(e0, e1);
                ep[2*t+1] = h2pack(e2, e3);
            } else {
                ep[2*t] = 0u; ep[2*t+1] = 0u;
            }
        }

        // ---- U += E @ V ----
        const int kkmax = (tlim == 16) ? 8 : 4;
        for (int kk = 0; kk < kkmax; kk++) {
            int kv0 = kk*16 + c2;
#pragma unroll
            for (int nt = 0; nt < 4; nt++) {
                int d = nt*8 + (lane >> 2);
                unsigned b0 = *(const unsigned*)&Vt[d][kv0];
                unsigned b1 = *(const unsigned*)&Vt[d][kv0+8];
                mma16816(uf[nt], &ep[4*kk], b0, b1);
            }
        }
        __syncthreads();
    }

    // ---- write U, Z ----
    {
        int qrow = q0 + warp*16 + r;
        float* u0 = U + ((size_t)g*Nn + qrow)*32;
        float* u8 = u0 + 8*32;
#pragma unroll
        for (int nt = 0; nt < 4; nt++) {
            int d = nt*8 + c2;
            u0[d]   = uf[nt][0];
            u0[d+1] = uf[nt][1];
            u8[d]   = uf[nt][2];
            u8[d+1] = uf[nt][3];
        }
        z0 += __shfl_xor_sync(0xffffffffu, z0, 1);
        z0 += __shfl_xor_sync(0xffffffffu, z0, 2);
        z1 += __shfl_xor_sync(0xffffffffu, z1, 1);
        z1 += __shfl_xor_sync(0xffffffffu, z1, 2);
        if ((lane & 3) == 0) {
            Zp[(size_t)g*Nn + qrow]     = z0;
            Zp[(size_t)g*Nn + qrow + 8] = z1;
        }
    }
}

// ---------- finalize: local 3x3 logits + learnable tokens + softmax combine ----------
__global__ void attn_finalize(
    const float* __restrict__ qs, const float* __restrict__ qn,
    const float* __restrict__ kl, const float* __restrict__ vl,
    const float* __restrict__ U, const float* __restrict__ Zp,
    const float* __restrict__ lt, const float* __restrict__ lb,
    float* __restrict__ xo)
{
    int warp = blockIdx.x * 8 + (threadIdx.x >> 5);
    int lane = threadIdx.x & 31;
    int g = warp / Nn, n = warp - g*Nn;
    int b = g >> 2, h = g & 3;
    int hh = n / Hs, ww = n - hh*Hs;
    size_t qi = ((size_t)g*Nn + n)*32 + lane;
    float q = qs[qi];
    float qv = qn[qi];
    float z = 0.f, res = 0.f, res2 = 0.f;
#pragma unroll
    for (int k = 0; k < 9; k++) {
        int h2 = hh + k/3 - 1, w2 = ww + (k%3) - 1;
        bool ok = (h2 >= 0 && h2 < Hs && w2 >= 0 && w2 < Hs);
        int nb = h2*Hs + w2;
        float kv = 0.f, vv = 0.f;
        if (ok) {
            size_t bi = ((size_t)g*Nn + nb)*32 + lane;
            kv = kl[bi]; vv = vl[bi];
        }
        float lg = q * kv;
        float wl = qv * lt[(h*32 + lane)*9 + k];
#pragma unroll
        for (int d = 16; d >= 1; d >>= 1) {
            lg += __shfl_xor_sync(0xffffffffu, lg, d);
            wl += __shfl_xor_sync(0xffffffffu, wl, d);
        }
        float e = __expf(lg);
        z += e;
        res  += e * vv;
        res2 += (wl + lb[h*9 + k]) * vv;
    }
    float Z = Zp[(size_t)g*Nn + n] + z;
    float o = (U[qi] + res) / Z + res2;
    xo[((size_t)(b*Nn + n))*128 + h*32 + lane] = o;
}

// ---------- depthwise 3x3 + gelu * v ----------
__global__ void dwconv_kernel(const float* __restrict__ f1, const float* __restrict__ dww,
                              const float* __restrict__ dwb, float* __restrict__ gout)
{
    int t = blockIdx.x;
    int c = threadIdx.x;
    if (c >= HFn) return;
    int b = t / Nn, n = t - b*Nn;
    int hh = n / Hs, ww = n - hh*Hs;
    float acc = dwb[c];
#pragma unroll
    for (int k = 0; k < 9; k++) {
        int h2 = hh + k/3 - 1, w2 = ww + (k%3) - 1;
        if (h2 < 0 || h2 >= Hs || w2 < 0 || w2 >= Hs) continue;
        acc += f1[((size_t)(b*Nn + h2*Hs + w2))*682 + c] * dww[c*9 + k];
    }
    float v = f1[(size_t)t*682 + 341 + c];
    gout[(size_t)t*HFn + c] = gelu_exact(acc) * v;
}

extern "C" void kernel_launch(void* const* d_in, const int* in_sizes, int n_in,
                              void* d_out, int out_size)
{
    const float* x      = (const float*)d_in[0];
    const float* n1w    = (const float*)d_in[1];
    const float* n1b    = (const float*)d_in[2];
    const float* q_w    = (const float*)d_in[3];
    const float* q_b    = (const float*)d_in[4];
    const float* kv_w   = (const float*)d_in[5];
    const float* kv_b   = (const float*)d_in[6];
    const float* temp   = (const float*)d_in[7];
    const float* qe     = (const float*)d_in[8];
    const float* lt     = (const float*)d_in[9];
    const float* lb     = (const float*)d_in[10];
    const float* sr_w   = (const float*)d_in[11];
    const float* sr_b   = (const float*)d_in[12];
    const float* plnw   = (const float*)d_in[13];
    const float* plnb   = (const float*)d_in[14];
    const float* proj_w = (const float*)d_in[15];
    const float* proj_b = (const float*)d_in[16];
    const float* n2w    = (const float*)d_in[17];
    const float* n2b    = (const float*)d_in[18];
    const float* fc1_w  = (const float*)d_in[19];
    const float* fc1_b  = (const float*)d_in[20];
    const float* dw_w   = (const float*)d_in[21];
    const float* dw_b   = (const float*)d_in[22];
    const float* fc2_w  = (const float*)d_in[23];
    const float* fc2_b  = (const float*)d_in[24];
    float* out = (float*)d_out;

    float *yb, *t1, *qsb, *qnb, *klb, *vlb, *xpb, *kvpb, *kpb, *vpb;
    float *Ub, *Zpb, *attb, *x2b, *y2b, *f1b, *gbb;
    cudaGetSymbolAddress((void**)&yb,   g_y);
    cudaGetSymbolAddress((void**)&t1,   g_tmp1);
    cudaGetSymbolAddress((void**)&qsb,  g_qs);
    cudaGetSymbolAddress((void**)&qnb,  g_qn);
    cudaGetSymbolAddress((void**)&klb,  g_kl);
    cudaGetSymbolAddress((void**)&vlb,  g_vl);
    cudaGetSymbolAddress((void**)&xpb,  g_xp);
    cudaGetSymbolAddress((void**)&kvpb, g_kvp);
    cudaGetSymbolAddress((void**)&kpb,  g_kp);
    cudaGetSymbolAddress((void**)&vpb,  g_vp);
    cudaGetSymbolAddress((void**)&Ub,   g_U);
    cudaGetSymbolAddress((void**)&Zpb,  g_Zp);
    cudaGetSymbolAddress((void**)&attb, g_att);
    cudaGetSymbolAddress((void**)&x2b,  g_x2);
    cudaGetSymbolAddress((void**)&y2b,  g_y2);
    cudaGetSymbolAddress((void**)&f1b,  g_f1);
    cudaGetSymbolAddress((void**)&gbb,  g_gb);

    ln_kernel<<<TOK/8, 256>>>(x, n1w, n1b, yb);
    gemm_kernel<<<dim3(2,49), 256>>>(yb, 128, q_w,  q_b,  t1,       512, 128, 128, 0, nullptr);
    gemm_kernel<<<dim3(4,49), 256>>>(yb, 128, kv_w, kv_b, t1 + 128, 512, 256, 128, 0, nullptr);
    gemm_kernel<<<dim3(2,49), 256>>>(yb, 128, sr_w, sr_b, t1 + 384, 512, 128, 128, 0, nullptr);
    pointwise1<<<TOK/8, 256>>>(t1, temp, qe, plnw, plnb, qsb, qnb, klb, vlb, xpb);
    gemm_kernel<<<dim3(4,49), 256>>>(xpb, 128, kv_w, kv_b, kvpb, 256, 256, 128, 0, nullptr);
    pointwise2<<<TOK/8, 256>>>(kvpb, kpb, vpb);
    attn_pool_mma<<<dim3(49,8), 128>>>(qsb, kpb, vpb, Ub, Zpb);
    attn_finalize<<<Nn, 256>>>(qsb, qnb, klb, vlb, Ub, Zpb, lt, lb, attb);
    gemm_kernel<<<dim3(2,49), 256>>>(attb, 128, proj_w, proj_b, x2b, 128, 128, 128, 1, x);
    ln_kernel<<<TOK/8, 256>>>(x2b, n2w, n2b, y2b);
    gemm_kernel<<<dim3(11,49), 256>>>(y2b, 128, fc1_w, fc1_b, f1b, 682, 682, 128, 0, nullptr);
    dwconv_kernel<<<TOK, 384>>>(f1b, dw_w, dw_b, gbb);
    gemm_kernel<<<dim3(2,49), 256>>>(gbb, 341, fc2_w, fc2_b, out, 128, 128, 341, 2, x2b);
}